// round 8
// baseline (speedup 1.0000x reference)
#include <cuda_runtime.h>

// GRUAdder: B=1048576, T=4, I=2, H=16
// out = concat(hidden_table[B,4,16], sum_logits[B,4], carry[B,1], output_logits[B,5]) fp32

static constexpr int BATCH   = 1048576;
static constexpr int TT      = 4;
static constexpr int HH      = 16;
static constexpr int NG      = 48;   // 3*H gate rows
static constexpr int KP      = 8;    // H/2 k-pairs
static constexpr int THREADS = 128;
static constexpr int ELEMS   = 2;

typedef unsigned long long u64;

// ---- weights in constant memory (filled by async D2D copies in kernel_launch) ----
__constant__ __align__(16) float c_whh[NG * HH];  // [48][16] row-major
__constant__ __align__(16) float c_wih[NG * 2];   // [48][2]
__constant__ float c_bih[NG];
__constant__ float c_bhh[NG];
__constant__ __align__(16) float c_ws[HH];
__constant__ __align__(16) float c_wc[HH];
__constant__ float c_bs[1];
__constant__ float c_bc[1];

__device__ __forceinline__ u64 pack2(float lo, float hi) {
    u64 r; asm("mov.b64 %0, {%1, %2};" : "=l"(r) : "f"(lo), "f"(hi)); return r;
}
__device__ __forceinline__ float2 unpack2(u64 v) {
    float2 f; asm("mov.b64 {%0, %1}, %2;" : "=f"(f.x), "=f"(f.y) : "l"(v)); return f;
}
__device__ __forceinline__ void ffma2(u64 &d, u64 a, u64 b) {
    asm("fma.rn.f32x2 %0, %1, %2, %0;" : "+l"(d) : "l"(a), "l"(b));
}
__device__ __forceinline__ float hsum2(u64 v) { float2 f = unpack2(v); return f.x + f.y; }

// HW tanh (1 MUFU). max err ~1e-4, well within 1e-3 budget.
__device__ __forceinline__ float tanh_fast(float x) {
    float y; asm("tanh.approx.f32 %0, %1;" : "=f"(y) : "f"(x)); return y;
}
// sigmoid(x) = 0.5*tanh(x/2) + 0.5
__device__ __forceinline__ float sigmoid_fast(float x) {
    return fmaf(tanh_fast(0.5f * x), 0.5f, 0.5f);
}

__global__ void __launch_bounds__(THREADS, 4)
gru_adder_kernel(const float* __restrict__ x,   // [B,4,2]
                 float* __restrict__ out,
                 long long off_hid, long long off_sum,
                 long long off_car, long long off_log)
{
    // bias sums staged in smem (tiny crossbar traffic: 1 LDS.128 per j)
    __shared__ __align__(16) float4 s_bias4[HH];   // {brz[j], brz[16+j], b_ih[32+j], b_hh[32+j]}
    __shared__ float s_hnA[HH][THREADS];           // new-h staging, element A
    __shared__ float s_hnB[HH][THREADS];           // new-h staging, element B

    const int tid = threadIdx.x;
    if (tid < HH) {
        s_bias4[tid] = make_float4(c_bih[tid] + c_bhh[tid],
                                   c_bih[16 + tid] + c_bhh[16 + tid],
                                   c_bih[32 + tid],
                                   c_bhh[32 + tid]);
    }
    __syncthreads();

    const int base = blockIdx.x * (THREADS * ELEMS) + tid;
    const int eA = base;
    const int eB = base + THREADS;

    const float4* xpA4 = reinterpret_cast<const float4*>(x + (size_t)eA * (TT * 2));
    const float4* xpB4 = reinterpret_cast<const float4*>(x + (size_t)eB * (TT * 2));
    float4 xA0 = xpA4[0], xA1 = xpA4[1];
    float4 xB0 = xpB4[0], xB1 = xpB4[1];
    u64 xpA[TT] = { pack2(xA0.x, xA0.y), pack2(xA0.z, xA0.w),
                    pack2(xA1.x, xA1.y), pack2(xA1.z, xA1.w) };
    u64 xpB[TT] = { pack2(xB0.x, xB0.y), pack2(xB0.z, xB0.w),
                    pack2(xB1.x, xB1.y), pack2(xB1.z, xB1.w) };

    u64 h2A[KP], h2B[KP];
#pragma unroll
    for (int kk = 0; kk < KP; ++kk) { h2A[kk] = 0ull; h2B[kk] = 0ull; }

#pragma unroll
    for (int t = 0; t < TT; ++t) {
        const u64 xtA = xpA[t], xtB = xpB[t];
        const bool hh_on = (t != 0);   // compile-time per unrolled copy

        // ----- rolled gate loop (keeps registers bounded) -----
#pragma unroll 1
        for (int j = 0; j < HH; ++j) {
            const float4 bias = s_bias4[j];   // 1 LDS.128
            // input weights from const (warp-uniform addresses -> const port)
            const u64 wr0 = *reinterpret_cast<const u64*>(c_wih + j * 2);
            const u64 wz0 = *reinterpret_cast<const u64*>(c_wih + (16 + j) * 2);
            const u64 wn0 = *reinterpret_cast<const u64*>(c_wih + (32 + j) * 2);

            float grA, grB, gzA, gzB, npA, npB;
            if (hh_on) {
                u64 arA = pack2(bias.x, 0.0f), arB = arA;
                u64 azA = pack2(bias.y, 0.0f), azB = azA;
                u64 anA = pack2(bias.w, 0.0f), anB = anA;
                ffma2(arA, wr0, xtA); ffma2(arB, wr0, xtB);
                ffma2(azA, wz0, xtA); ffma2(azB, wz0, xtB);
                // hidden weights: const memory, 16B vector reads
                const ulonglong2* wr  = reinterpret_cast<const ulonglong2*>(c_whh + j * HH);
                const ulonglong2* wz  = reinterpret_cast<const ulonglong2*>(c_whh + (16 + j) * HH);
                const ulonglong2* wnh = reinterpret_cast<const ulonglong2*>(c_whh + (32 + j) * HH);
#pragma unroll
                for (int q = 0; q < 4; ++q) {
                    ulonglong2 a = wr[q];
                    ffma2(arA, a.x, h2A[2 * q]); ffma2(arA, a.y, h2A[2 * q + 1]);
                    ffma2(arB, a.x, h2B[2 * q]); ffma2(arB, a.y, h2B[2 * q + 1]);
                    ulonglong2 b = wz[q];
                    ffma2(azA, b.x, h2A[2 * q]); ffma2(azA, b.y, h2A[2 * q + 1]);
                    ffma2(azB, b.x, h2B[2 * q]); ffma2(azB, b.y, h2B[2 * q + 1]);
                    ulonglong2 c = wnh[q];
                    ffma2(anA, c.x, h2A[2 * q]); ffma2(anA, c.y, h2A[2 * q + 1]);
                    ffma2(anB, c.x, h2B[2 * q]); ffma2(anB, c.y, h2B[2 * q + 1]);
                }
                grA = hsum2(arA); grB = hsum2(arB);
                gzA = hsum2(azA); gzB = hsum2(azB);
                u64 aiA = pack2(bias.z, 0.0f), aiB = aiA;
                ffma2(aiA, wn0, xtA); ffma2(aiB, wn0, xtB);
                float rA = sigmoid_fast(grA), rB = sigmoid_fast(grB);
                npA = hsum2(aiA) + rA * hsum2(anA);
                npB = hsum2(aiB) + rB * hsum2(anB);
            } else {
                u64 arA = pack2(bias.x, 0.0f), arB = arA;
                u64 azA = pack2(bias.y, 0.0f), azB = azA;
                u64 aiA = pack2(bias.z, 0.0f), aiB = aiA;
                ffma2(arA, wr0, xtA); ffma2(arB, wr0, xtB);
                ffma2(azA, wz0, xtA); ffma2(azB, wz0, xtB);
                ffma2(aiA, wn0, xtA); ffma2(aiB, wn0, xtB);
                grA = hsum2(arA); grB = hsum2(arB);
                gzA = hsum2(azA); gzB = hsum2(azB);
                float rA = sigmoid_fast(grA), rB = sigmoid_fast(grB);
                npA = hsum2(aiA) + rA * bias.w;
                npB = hsum2(aiB) + rB * bias.w;
            }
            float zA = sigmoid_fast(gzA), zB = sigmoid_fast(gzB);
            float nA = tanh_fast(npA),    nB = tanh_fast(npB);
            float2 hpA = unpack2(h2A[j >> 1]);
            float2 hpB = unpack2(h2B[j >> 1]);
            float hoA = (j & 1) ? hpA.y : hpA.x;
            float hoB = (j & 1) ? hpB.y : hpB.x;
            s_hnA[j][tid] = nA + zA * (hoA - nA);
            s_hnB[j][tid] = nB + zB * (hoB - nB);
        }

        // commit staged new h (conflict-free, static indices)
#pragma unroll
        for (int kk = 0; kk < KP; ++kk) {
            h2A[kk] = pack2(s_hnA[2 * kk][tid], s_hnA[2 * kk + 1][tid]);
            h2B[kk] = pack2(s_hnB[2 * kk][tid], s_hnB[2 * kk + 1][tid]);
        }

        // sum logits (weights from const, static indices)
        u64 sa = pack2(c_bs[0], 0.0f), sb = sa;
#pragma unroll
        for (int kk = 0; kk < KP; ++kk) {
            u64 w = *reinterpret_cast<const u64*>(c_ws + 2 * kk);
            ffma2(sa, w, h2A[kk]);
            ffma2(sb, w, h2B[kk]);
        }
        float sA = hsum2(sa), sB = hsum2(sb);

        if (off_hid >= 0) {
            float4* poA = reinterpret_cast<float4*>(out + off_hid + ((size_t)eA * TT + t) * HH);
            float4* poB = reinterpret_cast<float4*>(out + off_hid + ((size_t)eB * TT + t) * HH);
#pragma unroll
            for (int q = 0; q < 4; ++q) {
                float2 a0 = unpack2(h2A[2 * q]), a1 = unpack2(h2A[2 * q + 1]);
                poA[q] = make_float4(a0.x, a0.y, a1.x, a1.y);
            }
#pragma unroll
            for (int q = 0; q < 4; ++q) {
                float2 b0 = unpack2(h2B[2 * q]), b1 = unpack2(h2B[2 * q + 1]);
                poB[q] = make_float4(b0.x, b0.y, b1.x, b1.y);
            }
        }
        if (off_sum >= 0) {
            out[off_sum + (size_t)eA * TT + t] = sA;
            out[off_sum + (size_t)eB * TT + t] = sB;
        }
        if (off_log >= 0) {
            out[off_log + (size_t)eA * (TT + 1) + t] = sA;
            out[off_log + (size_t)eB * (TT + 1) + t] = sB;
        }
    }

    // carry head
    u64 ca = pack2(c_bc[0], 0.0f), cb = ca;
#pragma unroll
    for (int kk = 0; kk < KP; ++kk) {
        u64 w = *reinterpret_cast<const u64*>(c_wc + 2 * kk);
        ffma2(ca, w, h2A[kk]);
        ffma2(cb, w, h2B[kk]);
    }
    float cA = hsum2(ca), cB = hsum2(cb);
    if (off_car >= 0) { out[off_car + eA] = cA; out[off_car + eB] = cB; }
    if (off_log >= 0) {
        out[off_log + (size_t)eA * (TT + 1) + TT] = cA;
        out[off_log + (size_t)eB * (TT + 1) + TT] = cB;
    }
}

extern "C" void kernel_launch(void* const* d_in, const int* in_sizes, int n_in,
                              void* d_out, int out_size)
{
    const float* x = (const float*)d_in[0];
    float* out = (float*)d_out;

    // Async D2D copies into constant bank (graph-capturable, no allocations).
    cudaMemcpyToSymbolAsync(c_wih, d_in[1], NG * 2 * sizeof(float), 0, cudaMemcpyDeviceToDevice, 0);
    cudaMemcpyToSymbolAsync(c_whh, d_in[2], NG * HH * sizeof(float), 0, cudaMemcpyDeviceToDevice, 0);
    cudaMemcpyToSymbolAsync(c_bih, d_in[3], NG * sizeof(float), 0, cudaMemcpyDeviceToDevice, 0);
    cudaMemcpyToSymbolAsync(c_bhh, d_in[4], NG * sizeof(float), 0, cudaMemcpyDeviceToDevice, 0);
    cudaMemcpyToSymbolAsync(c_ws,  d_in[5], HH * sizeof(float), 0, cudaMemcpyDeviceToDevice, 0);
    cudaMemcpyToSymbolAsync(c_bs,  d_in[6], sizeof(float), 0, cudaMemcpyDeviceToDevice, 0);
    cudaMemcpyToSymbolAsync(c_wc,  d_in[7], HH * sizeof(float), 0, cudaMemcpyDeviceToDevice, 0);
    cudaMemcpyToSymbolAsync(c_bc,  d_in[8], sizeof(float), 0, cudaMemcpyDeviceToDevice, 0);

    const long long HID = 0;
    const long long SUM = (long long)BATCH * TT * HH;          // 67108864
    const long long CAR = SUM + (long long)BATCH * TT;         // 71303168
    const long long LOG = CAR + (long long)BATCH;              // 72351744
    const long long FULL = LOG + (long long)BATCH * (TT + 1);  // 77594624

    long long oh = -1, os = -1, oc = -1, ol = -1;
    long long sz = (long long)out_size;
    if (sz == FULL)                               { oh = HID; os = SUM; oc = CAR; ol = LOG; }
    else if (sz == (long long)BATCH * TT * HH)    { oh = 0; }
    else if (sz == (long long)BATCH * (TT + 1))   { ol = 0; }
    else if (sz == (long long)BATCH * TT)         { os = 0; }
    else if (sz == (long long)BATCH)              { oc = 0; }
    else                                          { oh = HID; os = SUM; oc = CAR; ol = LOG; }

    const int blocks = BATCH / (THREADS * ELEMS);   // 4096
    gru_adder_kernel<<<blocks, THREADS>>>(x, out, oh, os, oc, ol);
}

// round 9
// speedup vs baseline: 1.0816x; 1.0816x over previous
#include <cuda_runtime.h>

// GRUAdder: B=1048576, T=4, I=2, H=16
// out = concat(hidden_table[B,4,16], sum_logits[B,4], carry[B,1], output_logits[B,5]) fp32

static constexpr int BATCH   = 1048576;
static constexpr int TT      = 4;
static constexpr int HH      = 16;
static constexpr int KP      = 8;    // H/2 k-pairs
static constexpr int THREADS = 128;
static constexpr int ELEMS   = 2;

typedef unsigned long long u64;

// ---- n-gate + head weights in constant memory (separate port from smem crossbar) ----
__constant__ __align__(16) float c_whhn[HH * HH]; // w_hh rows 32..47  [16][16]
__constant__ __align__(16) float c_wihn[HH * 2];  // w_ih rows 32..47  [16][2]
__constant__ __align__(16) float c_ws[HH];
__constant__ __align__(16) float c_wc[HH];
__constant__ float c_bs[1];
__constant__ float c_bc[1];

__device__ __forceinline__ u64 pack2(float lo, float hi) {
    u64 r; asm("mov.b64 %0, {%1, %2};" : "=l"(r) : "f"(lo), "f"(hi)); return r;
}
__device__ __forceinline__ float2 unpack2(u64 v) {
    float2 f; asm("mov.b64 {%0, %1}, %2;" : "=f"(f.x), "=f"(f.y) : "l"(v)); return f;
}
__device__ __forceinline__ void ffma2(u64 &d, u64 a, u64 b) {
    asm("fma.rn.f32x2 %0, %1, %2, %0;" : "+l"(d) : "l"(a), "l"(b));
}
__device__ __forceinline__ float hsum2(u64 v) { float2 f = unpack2(v); return f.x + f.y; }

__device__ __forceinline__ float tanh_fast(float x) {
    float y; asm("tanh.approx.f32 %0, %1;" : "=f"(y) : "f"(x)); return y;
}
__device__ __forceinline__ float sigmoid_fast(float x) {
    return fmaf(tanh_fast(0.5f * x), 0.5f, 0.5f);
}

__global__ void __launch_bounds__(THREADS, 5)
gru_adder_kernel(const float* __restrict__ x,       // [B,4,2]
                 const float* __restrict__ w_ih,    // [48,2]
                 const float* __restrict__ w_hh,    // [48,16]
                 const float* __restrict__ b_ih,    // [48]
                 const float* __restrict__ b_hh,    // [48]
                 float* __restrict__ out,
                 long long off_hid, long long off_sum,
                 long long off_car, long long off_log)
{
    // r,z hidden weights + biases + r,z input weights in SMEM (crossbar port)
    __shared__ __align__(16) u64 s_whh2[2 * HH][KP];   // rows 0..31 (r, z)
    __shared__ __align__(16) ulonglong2 s_wihrz[HH];   // { wih2[j], wih2[16+j] }
    __shared__ __align__(16) float4 s_bias4[HH];       // {brz, bzz, b_ih_n, b_hh_n}
    __shared__ float s_hnA[HH][THREADS];
    __shared__ float s_hnB[HH][THREADS];

    const int tid = threadIdx.x;
    for (int i = tid; i < 2 * HH * KP; i += THREADS) {
        int g = i / KP, kk = i % KP;
        s_whh2[g][kk] = pack2(w_hh[g * HH + 2 * kk], w_hh[g * HH + 2 * kk + 1]);
    }
    if (tid < HH) {
        ulonglong2 wrz;
        wrz.x = pack2(w_ih[tid * 2],        w_ih[tid * 2 + 1]);
        wrz.y = pack2(w_ih[(16 + tid) * 2], w_ih[(16 + tid) * 2 + 1]);
        s_wihrz[tid] = wrz;
        s_bias4[tid] = make_float4(b_ih[tid] + b_hh[tid],
                                   b_ih[16 + tid] + b_hh[16 + tid],
                                   b_ih[32 + tid],
                                   b_hh[32 + tid]);
    }
    __syncthreads();

    const int base = blockIdx.x * (THREADS * ELEMS) + tid;
    const int eA = base;
    const int eB = base + THREADS;

    const float2* xA2 = reinterpret_cast<const float2*>(x + (size_t)eA * (TT * 2));
    const float2* xB2 = reinterpret_cast<const float2*>(x + (size_t)eB * (TT * 2));

    u64 h2A[KP], h2B[KP];
#pragma unroll
    for (int kk = 0; kk < KP; ++kk) { h2A[kk] = 0ull; h2B[kk] = 0ull; }

#pragma unroll
    for (int t = 0; t < TT; ++t) {
        float2 xa = __ldg(xA2 + t);
        float2 xb = __ldg(xB2 + t);
        const u64 xtA = pack2(xa.x, xa.y);
        const u64 xtB = pack2(xb.x, xb.y);
        const bool hh_on = (t != 0);   // compile-time per unrolled copy

        // ----- rolled gate loop (keeps registers bounded) -----
#pragma unroll 1
        for (int j = 0; j < HH; ++j) {
            const float4 bias = s_bias4[j];        // LDS.128
            const ulonglong2 wrz = s_wihrz[j];     // LDS.128
            const u64 wn0 = *reinterpret_cast<const u64*>(c_wihn + j * 2);  // LDC.64

            float grA, grB, gzA, gzB, npA, npB;
            if (hh_on) {
                u64 arA = pack2(bias.x, 0.0f), arB = arA;
                u64 azA = pack2(bias.y, 0.0f), azB = azA;
                u64 anA = pack2(bias.w, 0.0f), anB = anA;
                ffma2(arA, wrz.x, xtA); ffma2(arB, wrz.x, xtB);
                ffma2(azA, wrz.y, xtA); ffma2(azB, wrz.y, xtB);
                const ulonglong2* wr  = reinterpret_cast<const ulonglong2*>(s_whh2[j]);       // smem
                const ulonglong2* wz  = reinterpret_cast<const ulonglong2*>(s_whh2[16 + j]);  // smem
                const ulonglong2* wnh = reinterpret_cast<const ulonglong2*>(c_whhn + j * HH); // const
#pragma unroll
                for (int q = 0; q < 4; ++q) {
                    ulonglong2 a = wr[q];     // LDS.128 (crossbar)
                    ffma2(arA, a.x, h2A[2 * q]); ffma2(arA, a.y, h2A[2 * q + 1]);
                    ffma2(arB, a.x, h2B[2 * q]); ffma2(arB, a.y, h2B[2 * q + 1]);
                    ulonglong2 b = wz[q];     // LDS.128 (crossbar)
                    ffma2(azA, b.x, h2A[2 * q]); ffma2(azA, b.y, h2A[2 * q + 1]);
                    ffma2(azB, b.x, h2B[2 * q]); ffma2(azB, b.y, h2B[2 * q + 1]);
                    ulonglong2 c = wnh[q];    // LDC.128 (const port)
                    ffma2(anA, c.x, h2A[2 * q]); ffma2(anA, c.y, h2A[2 * q + 1]);
                    ffma2(anB, c.x, h2B[2 * q]); ffma2(anB, c.y, h2B[2 * q + 1]);
                }
                grA = hsum2(arA); grB = hsum2(arB);
                gzA = hsum2(azA); gzB = hsum2(azB);
                u64 aiA = pack2(bias.z, 0.0f), aiB = aiA;
                ffma2(aiA, wn0, xtA); ffma2(aiB, wn0, xtB);
                float rA = sigmoid_fast(grA), rB = sigmoid_fast(grB);
                npA = hsum2(aiA) + rA * hsum2(anA);
                npB = hsum2(aiB) + rB * hsum2(anB);
            } else {
                u64 arA = pack2(bias.x, 0.0f), arB = arA;
                u64 azA = pack2(bias.y, 0.0f), azB = azA;
                u64 aiA = pack2(bias.z, 0.0f), aiB = aiA;
                ffma2(arA, wrz.x, xtA); ffma2(arB, wrz.x, xtB);
                ffma2(azA, wrz.y, xtA); ffma2(azB, wrz.y, xtB);
                ffma2(aiA, wn0, xtA);   ffma2(aiB, wn0, xtB);
                grA = hsum2(arA); grB = hsum2(arB);
                gzA = hsum2(azA); gzB = hsum2(azB);
                float rA = sigmoid_fast(grA), rB = sigmoid_fast(grB);
                npA = hsum2(aiA) + rA * bias.w;
                npB = hsum2(aiB) + rB * bias.w;
            }
            float zA = sigmoid_fast(gzA), zB = sigmoid_fast(gzB);
            float nA = tanh_fast(npA),    nB = tanh_fast(npB);
            float2 hpA = unpack2(h2A[j >> 1]);
            float2 hpB = unpack2(h2B[j >> 1]);
            float hoA = (j & 1) ? hpA.y : hpA.x;
            float hoB = (j & 1) ? hpB.y : hpB.x;
            s_hnA[j][tid] = nA + zA * (hoA - nA);
            s_hnB[j][tid] = nB + zB * (hoB - nB);
        }

        // commit staged new h (conflict-free, static indices)
#pragma unroll
        for (int kk = 0; kk < KP; ++kk) {
            h2A[kk] = pack2(s_hnA[2 * kk][tid], s_hnA[2 * kk + 1][tid]);
            h2B[kk] = pack2(s_hnB[2 * kk][tid], s_hnB[2 * kk + 1][tid]);
        }

        // sum logits (head weights from const)
        u64 sa = pack2(c_bs[0], 0.0f), sb = sa;
#pragma unroll
        for (int kk = 0; kk < KP; ++kk) {
            u64 w = *reinterpret_cast<const u64*>(c_ws + 2 * kk);
            ffma2(sa, w, h2A[kk]);
            ffma2(sb, w, h2B[kk]);
        }
        float sA = hsum2(sa), sB = hsum2(sb);

        if (off_hid >= 0) {
            float4* poA = reinterpret_cast<float4*>(out + off_hid + ((size_t)eA * TT + t) * HH);
            float4* poB = reinterpret_cast<float4*>(out + off_hid + ((size_t)eB * TT + t) * HH);
#pragma unroll
            for (int q = 0; q < 4; ++q) {
                float2 a0 = unpack2(h2A[2 * q]), a1 = unpack2(h2A[2 * q + 1]);
                poA[q] = make_float4(a0.x, a0.y, a1.x, a1.y);
            }
#pragma unroll
            for (int q = 0; q < 4; ++q) {
                float2 b0 = unpack2(h2B[2 * q]), b1 = unpack2(h2B[2 * q + 1]);
                poB[q] = make_float4(b0.x, b0.y, b1.x, b1.y);
            }
        }
        if (off_sum >= 0) {
            out[off_sum + (size_t)eA * TT + t] = sA;
            out[off_sum + (size_t)eB * TT + t] = sB;
        }
        if (off_log >= 0) {
            out[off_log + (size_t)eA * (TT + 1) + t] = sA;
            out[off_log + (size_t)eB * (TT + 1) + t] = sB;
        }
    }

    // carry head
    u64 ca = pack2(c_bc[0], 0.0f), cb = ca;
#pragma unroll
    for (int kk = 0; kk < KP; ++kk) {
        u64 w = *reinterpret_cast<const u64*>(c_wc + 2 * kk);
        ffma2(ca, w, h2A[kk]);
        ffma2(cb, w, h2B[kk]);
    }
    float cA = hsum2(ca), cB = hsum2(cb);
    if (off_car >= 0) { out[off_car + eA] = cA; out[off_car + eB] = cB; }
    if (off_log >= 0) {
        out[off_log + (size_t)eA * (TT + 1) + TT] = cA;
        out[off_log + (size_t)eB * (TT + 1) + TT] = cB;
    }
}

extern "C" void kernel_launch(void* const* d_in, const int* in_sizes, int n_in,
                              void* d_out, int out_size)
{
    const float* x    = (const float*)d_in[0];
    const float* w_ih = (const float*)d_in[1];
    const float* w_hh = (const float*)d_in[2];
    const float* b_ih = (const float*)d_in[3];
    const float* b_hh = (const float*)d_in[4];
    float* out = (float*)d_out;

    // n-gate rows (32..47) + heads into constant memory (graph-capturable D2D)
    cudaMemcpyToSymbolAsync(c_whhn, (const char*)d_in[2] + 32 * HH * sizeof(float),
                            HH * HH * sizeof(float), 0, cudaMemcpyDeviceToDevice, 0);
    cudaMemcpyToSymbolAsync(c_wihn, (const char*)d_in[1] + 32 * 2 * sizeof(float),
                            HH * 2 * sizeof(float), 0, cudaMemcpyDeviceToDevice, 0);
    cudaMemcpyToSymbolAsync(c_ws, d_in[5], HH * sizeof(float), 0, cudaMemcpyDeviceToDevice, 0);
    cudaMemcpyToSymbolAsync(c_bs, d_in[6], sizeof(float), 0, cudaMemcpyDeviceToDevice, 0);
    cudaMemcpyToSymbolAsync(c_wc, d_in[7], HH * sizeof(float), 0, cudaMemcpyDeviceToDevice, 0);
    cudaMemcpyToSymbolAsync(c_bc, d_in[8], sizeof(float), 0, cudaMemcpyDeviceToDevice, 0);

    const long long HID = 0;
    const long long SUM = (long long)BATCH * TT * HH;          // 67108864
    const long long CAR = SUM + (long long)BATCH * TT;         // 71303168
    const long long LOG = CAR + (long long)BATCH;              // 72351744
    const long long FULL = LOG + (long long)BATCH * (TT + 1);  // 77594624

    long long oh = -1, os = -1, oc = -1, ol = -1;
    long long sz = (long long)out_size;
    if (sz == FULL)                               { oh = HID; os = SUM; oc = CAR; ol = LOG; }
    else if (sz == (long long)BATCH * TT * HH)    { oh = 0; }
    else if (sz == (long long)BATCH * (TT + 1))   { ol = 0; }
    else if (sz == (long long)BATCH * TT)         { os = 0; }
    else if (sz == (long long)BATCH)              { oc = 0; }
    else                                          { oh = HID; os = SUM; oc = CAR; ol = LOG; }

    const int blocks = BATCH / (THREADS * ELEMS);   // 4096
    gru_adder_kernel<<<blocks, THREADS>>>(x, w_ih, w_hh, b_ih, b_hh,
                                          out, oh, os, oc, ol);
}

// round 10
// speedup vs baseline: 1.1307x; 1.0454x over previous
#include <cuda_runtime.h>

// GRUAdder: B=1048576, T=4, I=2, H=16
// out = concat(hidden_table[B,4,16], sum_logits[B,4], carry[B,1], output_logits[B,5]) fp32

static constexpr int BATCH   = 1048576;
static constexpr int TT      = 4;
static constexpr int HH      = 16;
static constexpr int KP      = 8;    // H/2 k-pairs
static constexpr int THREADS = 128;
static constexpr int ELEMS   = 3;
static constexpr int SPAN    = THREADS * ELEMS;   // 384

typedef unsigned long long u64;

// ---- n-gate + head weights in constant memory (separate port from smem crossbar) ----
__constant__ __align__(16) float c_whhn[HH * HH]; // w_hh rows 32..47  [16][16]
__constant__ __align__(16) float c_wihn[HH * 2];  // w_ih rows 32..47  [16][2]
__constant__ __align__(16) float c_ws[HH];
__constant__ __align__(16) float c_wc[HH];
__constant__ float c_bs[1];
__constant__ float c_bc[1];

__device__ __forceinline__ u64 pack2(float lo, float hi) {
    u64 r; asm("mov.b64 %0, {%1, %2};" : "=l"(r) : "f"(lo), "f"(hi)); return r;
}
__device__ __forceinline__ float2 unpack2(u64 v) {
    float2 f; asm("mov.b64 {%0, %1}, %2;" : "=f"(f.x), "=f"(f.y) : "l"(v)); return f;
}
__device__ __forceinline__ void ffma2(u64 &d, u64 a, u64 b) {
    asm("fma.rn.f32x2 %0, %1, %2, %0;" : "+l"(d) : "l"(a), "l"(b));
}
__device__ __forceinline__ float hsum2(u64 v) { float2 f = unpack2(v); return f.x + f.y; }

__device__ __forceinline__ float tanh_fast(float x) {
    float y; asm("tanh.approx.f32 %0, %1;" : "=f"(y) : "f"(x)); return y;
}
__device__ __forceinline__ float sigmoid_fast(float x) {
    return fmaf(tanh_fast(0.5f * x), 0.5f, 0.5f);
}

__global__ void __launch_bounds__(THREADS, 4)
gru_adder_kernel(const float* __restrict__ x,       // [B,4,2]
                 const float* __restrict__ w_ih,    // [48,2]
                 const float* __restrict__ w_hh,    // [48,16]
                 const float* __restrict__ b_ih,    // [48]
                 const float* __restrict__ b_hh,    // [48]
                 float* __restrict__ out,
                 long long off_hid, long long off_sum,
                 long long off_car, long long off_log)
{
    // r,z hidden weights + biases + r,z input weights in SMEM (crossbar port)
    __shared__ __align__(16) u64 s_whh2[2 * HH][KP];   // rows 0..31 (r, z)
    __shared__ __align__(16) ulonglong2 s_wihrz[HH];   // { wih2[j], wih2[16+j] }
    __shared__ __align__(16) float4 s_bias4[HH];       // {b_r, b_z, b_ih_n, b_hh_n}
    __shared__ float s_hn[ELEMS][HH][THREADS];         // new-h staging per element

    const int tid = threadIdx.x;
    for (int i = tid; i < 2 * HH * KP; i += THREADS) {
        int g = i / KP, kk = i % KP;
        s_whh2[g][kk] = pack2(w_hh[g * HH + 2 * kk], w_hh[g * HH + 2 * kk + 1]);
    }
    if (tid < HH) {
        ulonglong2 wrz;
        wrz.x = pack2(w_ih[tid * 2],        w_ih[tid * 2 + 1]);
        wrz.y = pack2(w_ih[(16 + tid) * 2], w_ih[(16 + tid) * 2 + 1]);
        s_wihrz[tid] = wrz;
        s_bias4[tid] = make_float4(b_ih[tid] + b_hh[tid],
                                   b_ih[16 + tid] + b_hh[16 + tid],
                                   b_ih[32 + tid],
                                   b_hh[32 + tid]);
    }
    __syncthreads();

    // element indices (last block may be partial: clamp loads, predicate stores)
    long long idx[ELEMS];
    bool valid[ELEMS];
    long long eidx[ELEMS];
#pragma unroll
    for (int e = 0; e < ELEMS; ++e) {
        idx[e] = (long long)blockIdx.x * SPAN + e * THREADS + tid;
        valid[e] = idx[e] < (long long)BATCH;
        eidx[e] = valid[e] ? idx[e] : (long long)(BATCH - 1);
    }

    u64 h2[ELEMS][KP];
#pragma unroll
    for (int e = 0; e < ELEMS; ++e)
#pragma unroll
        for (int kk = 0; kk < KP; ++kk) h2[e][kk] = 0ull;

#pragma unroll
    for (int t = 0; t < TT; ++t) {
        u64 xt[ELEMS];
#pragma unroll
        for (int e = 0; e < ELEMS; ++e) {
            float2 xv = __ldg(reinterpret_cast<const float2*>(x + eidx[e] * (TT * 2)) + t);
            xt[e] = pack2(xv.x, xv.y);
        }
        const bool hh_on = (t != 0);   // compile-time per unrolled copy

        // ----- rolled gate loop (keeps registers bounded) -----
#pragma unroll 1
        for (int j = 0; j < HH; ++j) {
            const float4 bias = s_bias4[j];        // LDS.128
            const ulonglong2 wrz = s_wihrz[j];     // LDS.128
            const u64 wn0 = *reinterpret_cast<const u64*>(c_wihn + j * 2);  // const port

            u64 ar[ELEMS], az[ELEMS], an[ELEMS];
#pragma unroll
            for (int e = 0; e < ELEMS; ++e) {
                ar[e] = pack2(bias.x, 0.0f);
                az[e] = pack2(bias.y, 0.0f);
                an[e] = pack2(bias.w, 0.0f);
                ffma2(ar[e], wrz.x, xt[e]);
                ffma2(az[e], wrz.y, xt[e]);
            }

            if (hh_on) {
                const ulonglong2* wr  = reinterpret_cast<const ulonglong2*>(s_whh2[j]);       // smem
                const ulonglong2* wz  = reinterpret_cast<const ulonglong2*>(s_whh2[16 + j]);  // smem
                const ulonglong2* wnh = reinterpret_cast<const ulonglong2*>(c_whhn + j * HH); // const
#pragma unroll
                for (int q = 0; q < 4; ++q) {
                    ulonglong2 a = wr[q];     // LDS.128 feeds 6 FFMA2 (3 elems)
#pragma unroll
                    for (int e = 0; e < ELEMS; ++e) {
                        ffma2(ar[e], a.x, h2[e][2 * q]); ffma2(ar[e], a.y, h2[e][2 * q + 1]);
                    }
                    ulonglong2 b = wz[q];
#pragma unroll
                    for (int e = 0; e < ELEMS; ++e) {
                        ffma2(az[e], b.x, h2[e][2 * q]); ffma2(az[e], b.y, h2[e][2 * q + 1]);
                    }
                    ulonglong2 c = wnh[q];    // const port
#pragma unroll
                    for (int e = 0; e < ELEMS; ++e) {
                        ffma2(an[e], c.x, h2[e][2 * q]); ffma2(an[e], c.y, h2[e][2 * q + 1]);
                    }
                }
            }

#pragma unroll
            for (int e = 0; e < ELEMS; ++e) {
                float gr = hsum2(ar[e]);
                float gz = hsum2(az[e]);
                u64 ai = pack2(bias.z, 0.0f);
                ffma2(ai, wn0, xt[e]);
                float r = sigmoid_fast(gr);
                float np = hh_on ? (hsum2(ai) + r * hsum2(an[e]))
                                 : (hsum2(ai) + r * bias.w);
                float z = sigmoid_fast(gz);
                float n = tanh_fast(np);
                float2 hp = unpack2(h2[e][j >> 1]);
                float ho = (j & 1) ? hp.y : hp.x;
                s_hn[e][j][tid] = n + z * (ho - n);
            }
        }

        // commit staged new h (conflict-free, static indices)
#pragma unroll
        for (int e = 0; e < ELEMS; ++e)
#pragma unroll
            for (int kk = 0; kk < KP; ++kk)
                h2[e][kk] = pack2(s_hn[e][2 * kk][tid], s_hn[e][2 * kk + 1][tid]);

        // sum logits + stores (head weights from const)
#pragma unroll
        for (int e = 0; e < ELEMS; ++e) {
            u64 sa = pack2(c_bs[0], 0.0f);
#pragma unroll
            for (int kk = 0; kk < KP; ++kk)
                ffma2(sa, *reinterpret_cast<const u64*>(c_ws + 2 * kk), h2[e][kk]);
            float sO = hsum2(sa);

            if (valid[e]) {
                if (off_hid >= 0) {
                    float4* po = reinterpret_cast<float4*>(out + off_hid + (idx[e] * TT + t) * HH);
#pragma unroll
                    for (int q = 0; q < 4; ++q) {
                        float2 a0 = unpack2(h2[e][2 * q]), a1 = unpack2(h2[e][2 * q + 1]);
                        po[q] = make_float4(a0.x, a0.y, a1.x, a1.y);
                    }
                }
                if (off_sum >= 0) out[off_sum + idx[e] * TT + t] = sO;
                if (off_log >= 0) out[off_log + idx[e] * (TT + 1) + t] = sO;
            }
        }
    }

    // carry head
#pragma unroll
    for (int e = 0; e < ELEMS; ++e) {
        u64 ca = pack2(c_bc[0], 0.0f);
#pragma unroll
        for (int kk = 0; kk < KP; ++kk)
            ffma2(ca, *reinterpret_cast<const u64*>(c_wc + 2 * kk), h2[e][kk]);
        float cO = hsum2(ca);
        if (valid[e]) {
            if (off_car >= 0) out[off_car + idx[e]] = cO;
            if (off_log >= 0) out[off_log + idx[e] * (TT + 1) + TT] = cO;
        }
    }
}

extern "C" void kernel_launch(void* const* d_in, const int* in_sizes, int n_in,
                              void* d_out, int out_size)
{
    const float* x    = (const float*)d_in[0];
    const float* w_ih = (const float*)d_in[1];
    const float* w_hh = (const float*)d_in[2];
    const float* b_ih = (const float*)d_in[3];
    const float* b_hh = (const float*)d_in[4];
    float* out = (float*)d_out;

    // n-gate rows (32..47) + heads into constant memory (graph-capturable D2D)
    cudaMemcpyToSymbolAsync(c_whhn, (const char*)d_in[2] + 32 * HH * sizeof(float),
                            HH * HH * sizeof(float), 0, cudaMemcpyDeviceToDevice, 0);
    cudaMemcpyToSymbolAsync(c_wihn, (const char*)d_in[1] + 32 * 2 * sizeof(float),
                            HH * 2 * sizeof(float), 0, cudaMemcpyDeviceToDevice, 0);
    cudaMemcpyToSymbolAsync(c_ws, d_in[5], HH * sizeof(float), 0, cudaMemcpyDeviceToDevice, 0);
    cudaMemcpyToSymbolAsync(c_bs, d_in[6], sizeof(float), 0, cudaMemcpyDeviceToDevice, 0);
    cudaMemcpyToSymbolAsync(c_wc, d_in[7], HH * sizeof(float), 0, cudaMemcpyDeviceToDevice, 0);
    cudaMemcpyToSymbolAsync(c_bc, d_in[8], sizeof(float), 0, cudaMemcpyDeviceToDevice, 0);

    const long long HID = 0;
    const long long SUM = (long long)BATCH * TT * HH;          // 67108864
    const long long CAR = SUM + (long long)BATCH * TT;         // 71303168
    const long long LOG = CAR + (long long)BATCH;              // 72351744
    const long long FULL = LOG + (long long)BATCH * (TT + 1);  // 77594624

    long long oh = -1, os = -1, oc = -1, ol = -1;
    long long sz = (long long)out_size;
    if (sz == FULL)                               { oh = HID; os = SUM; oc = CAR; ol = LOG; }
    else if (sz == (long long)BATCH * TT * HH)    { oh = 0; }
    else if (sz == (long long)BATCH * (TT + 1))   { ol = 0; }
    else if (sz == (long long)BATCH * TT)         { os = 0; }
    else if (sz == (long long)BATCH)              { oc = 0; }
    else                                          { oh = HID; os = SUM; oc = CAR; ol = LOG; }

    const int blocks = (BATCH + SPAN - 1) / SPAN;   // 2731
    gru_adder_kernel<<<blocks, THREADS>>>(x, w_ih, w_hh, b_ih, b_hh,
                                          out, oh, os, oc, ol);
}

// round 11
// speedup vs baseline: 1.2421x; 1.0985x over previous
#include <cuda_runtime.h>

// GRUAdder: B=1048576, T=4, I=2, H=16
// out = concat(hidden_table[B,4,16], sum_logits[B,4], carry[B,1], output_logits[B,5]) fp32

static constexpr int BATCH   = 1048576;
static constexpr int TT      = 4;
static constexpr int HH      = 16;
static constexpr int KP      = 8;    // H/2 k-pairs
static constexpr int THREADS = 128;
static constexpr int ELEMS   = 3;
static constexpr int SPAN    = THREADS * ELEMS;   // 384
static constexpr int COLP    = THREADS + 1;       // padded staging stride

typedef unsigned long long u64;

// ---- n-gate + head weights in constant memory (separate port from smem crossbar) ----
__constant__ __align__(16) float c_whhn[HH * HH]; // w_hh rows 32..47  [16][16]
__constant__ __align__(16) float c_wihn[HH * 2];  // w_ih rows 32..47  [16][2]
__constant__ __align__(16) float c_ws[HH];
__constant__ __align__(16) float c_wc[HH];
__constant__ float c_bs[1];
__constant__ float c_bc[1];

__device__ __forceinline__ u64 pack2(float lo, float hi) {
    u64 r; asm("mov.b64 %0, {%1, %2};" : "=l"(r) : "f"(lo), "f"(hi)); return r;
}
__device__ __forceinline__ float2 unpack2(u64 v) {
    float2 f; asm("mov.b64 {%0, %1}, %2;" : "=f"(f.x), "=f"(f.y) : "l"(v)); return f;
}
__device__ __forceinline__ void ffma2(u64 &d, u64 a, u64 b) {
    asm("fma.rn.f32x2 %0, %1, %2, %0;" : "+l"(d) : "l"(a), "l"(b));
}
__device__ __forceinline__ float hsum2(u64 v) { float2 f = unpack2(v); return f.x + f.y; }

__device__ __forceinline__ float tanh_fast(float x) {
    float y; asm("tanh.approx.f32 %0, %1;" : "=f"(y) : "f"(x)); return y;
}
__device__ __forceinline__ float sigmoid_fast(float x) {
    return fmaf(tanh_fast(0.5f * x), 0.5f, 0.5f);
}

__global__ void __launch_bounds__(THREADS, 4)
gru_adder_kernel(const float* __restrict__ x,       // [B,4,2]
                 const float* __restrict__ w_ih,    // [48,2]
                 const float* __restrict__ w_hh,    // [48,16]
                 const float* __restrict__ b_ih,    // [48]
                 const float* __restrict__ b_hh,    // [48]
                 float* __restrict__ out,
                 long long off_hid, long long off_sum,
                 long long off_car, long long off_log)
{
    // r,z hidden weights + biases + r,z input weights in SMEM (crossbar port)
    __shared__ __align__(16) u64 s_whh2[2 * HH][KP];   // rows 0..31 (r, z)
    __shared__ __align__(16) ulonglong2 s_wihrz[HH];   // { wih2[j], wih2[16+j] }
    __shared__ __align__(16) float4 s_bias4[HH];       // {b_r, b_z, b_ih_n, b_hh_n}
    __shared__ float s_hn[ELEMS][HH][COLP];            // new-h staging (padded)

    const int tid = threadIdx.x;
    for (int i = tid; i < 2 * HH * KP; i += THREADS) {
        int g = i / KP, kk = i % KP;
        s_whh2[g][kk] = pack2(w_hh[g * HH + 2 * kk], w_hh[g * HH + 2 * kk + 1]);
    }
    if (tid < HH) {
        ulonglong2 wrz;
        wrz.x = pack2(w_ih[tid * 2],        w_ih[tid * 2 + 1]);
        wrz.y = pack2(w_ih[(16 + tid) * 2], w_ih[(16 + tid) * 2 + 1]);
        s_wihrz[tid] = wrz;
        s_bias4[tid] = make_float4(b_ih[tid] + b_hh[tid],
                                   b_ih[16 + tid] + b_hh[16 + tid],
                                   b_ih[32 + tid],
                                   b_hh[32 + tid]);
    }
    __syncthreads();

    // element indices (last block may be partial: clamp loads, predicate stores)
    const long long gbase = (long long)blockIdx.x * SPAN;
    long long idx[ELEMS];
    bool valid[ELEMS];
    long long eidx[ELEMS];
#pragma unroll
    for (int e = 0; e < ELEMS; ++e) {
        idx[e] = gbase + e * THREADS + tid;
        valid[e] = idx[e] < (long long)BATCH;
        eidx[e] = valid[e] ? idx[e] : (long long)(BATCH - 1);
    }

    u64 h2[ELEMS][KP];
#pragma unroll
    for (int e = 0; e < ELEMS; ++e)
#pragma unroll
        for (int kk = 0; kk < KP; ++kk) h2[e][kk] = 0ull;

#pragma unroll
    for (int t = 0; t < TT; ++t) {
        u64 xt[ELEMS];
#pragma unroll
        for (int e = 0; e < ELEMS; ++e) {
            float2 xv = __ldg(reinterpret_cast<const float2*>(x + eidx[e] * (TT * 2)) + t);
            xt[e] = pack2(xv.x, xv.y);
        }
        const bool hh_on = (t != 0);   // compile-time per unrolled copy

        // ----- rolled gate loop (keeps registers bounded) -----
#pragma unroll 1
        for (int j = 0; j < HH; ++j) {
            const float4 bias = s_bias4[j];        // LDS.128
            const ulonglong2 wrz = s_wihrz[j];     // LDS.128
            const u64 wn0 = *reinterpret_cast<const u64*>(c_wihn + j * 2);  // const port

            u64 ar[ELEMS], az[ELEMS], an[ELEMS];
#pragma unroll
            for (int e = 0; e < ELEMS; ++e) {
                ar[e] = pack2(bias.x, 0.0f);
                az[e] = pack2(bias.y, 0.0f);
                an[e] = pack2(bias.w, 0.0f);
                ffma2(ar[e], wrz.x, xt[e]);
                ffma2(az[e], wrz.y, xt[e]);
            }

            if (hh_on) {
                const ulonglong2* wr  = reinterpret_cast<const ulonglong2*>(s_whh2[j]);       // smem
                const ulonglong2* wz  = reinterpret_cast<const ulonglong2*>(s_whh2[16 + j]);  // smem
                const ulonglong2* wnh = reinterpret_cast<const ulonglong2*>(c_whhn + j * HH); // const
#pragma unroll
                for (int q = 0; q < 4; ++q) {
                    ulonglong2 a = wr[q];     // LDS.128 feeds 6 FFMA2 (3 elems)
#pragma unroll
                    for (int e = 0; e < ELEMS; ++e) {
                        ffma2(ar[e], a.x, h2[e][2 * q]); ffma2(ar[e], a.y, h2[e][2 * q + 1]);
                    }
                    ulonglong2 b = wz[q];
#pragma unroll
                    for (int e = 0; e < ELEMS; ++e) {
                        ffma2(az[e], b.x, h2[e][2 * q]); ffma2(az[e], b.y, h2[e][2 * q + 1]);
                    }
                    ulonglong2 c = wnh[q];    // const port
#pragma unroll
                    for (int e = 0; e < ELEMS; ++e) {
                        ffma2(an[e], c.x, h2[e][2 * q]); ffma2(an[e], c.y, h2[e][2 * q + 1]);
                    }
                }
            }

#pragma unroll
            for (int e = 0; e < ELEMS; ++e) {
                float gr = hsum2(ar[e]);
                float gz = hsum2(az[e]);
                u64 ai = pack2(bias.z, 0.0f);
                ffma2(ai, wn0, xt[e]);
                float r = sigmoid_fast(gr);
                float np = hh_on ? (hsum2(ai) + r * hsum2(an[e]))
                                 : (hsum2(ai) + r * bias.w);
                float z = sigmoid_fast(gz);
                float n = tanh_fast(np);
                float2 hp = unpack2(h2[e][j >> 1]);
                float ho = (j & 1) ? hp.y : hp.x;
                s_hn[e][j][tid] = n + z * (ho - n);
            }
        }

        // commit staged new h (own column only — no race before barrier)
#pragma unroll
        for (int e = 0; e < ELEMS; ++e)
#pragma unroll
            for (int kk = 0; kk < KP; ++kk)
                h2[e][kk] = pack2(s_hn[e][2 * kk][tid], s_hn[e][2 * kk + 1][tid]);

        // ---- COALESCED hidden-table stores via staging smem ----
        if (off_hid >= 0) {
            __syncthreads();   // staging visible to all threads (block-uniform branch)
#pragma unroll
            for (int k = 0; k < 12; ++k) {
                int flat = k * THREADS + tid;       // 0..1535 = (elem_local, c4)
                int elem_local = flat >> 2;         // 0..383
                int c4 = (flat & 3) << 2;           // j0 in {0,4,8,12}
                int e = elem_local >> 7;
                int col = elem_local & 127;
                long long g = gbase + elem_local;   // == blockbase + e*128 + col
                if (g < (long long)BATCH) {
                    const float* sp = &s_hn[e][c4][col];
                    float4 v = make_float4(sp[0], sp[COLP], sp[2 * COLP], sp[3 * COLP]);
                    *reinterpret_cast<float4*>(out + off_hid + (g * TT + t) * HH + c4) = v;
                }
            }
            __syncthreads();   // protect staging before next t overwrites
        }

        // sum logits + small scattered stores (head weights from const)
#pragma unroll
        for (int e = 0; e < ELEMS; ++e) {
            u64 sa = pack2(c_bs[0], 0.0f);
#pragma unroll
            for (int kk = 0; kk < KP; ++kk)
                ffma2(sa, *reinterpret_cast<const u64*>(c_ws + 2 * kk), h2[e][kk]);
            float sO = hsum2(sa);

            if (valid[e]) {
                if (off_sum >= 0) out[off_sum + idx[e] * TT + t] = sO;
                if (off_log >= 0) out[off_log + idx[e] * (TT + 1) + t] = sO;
            }
        }
    }

    // carry head
#pragma unroll
    for (int e = 0; e < ELEMS; ++e) {
        u64 ca = pack2(c_bc[0], 0.0f);
#pragma unroll
        for (int kk = 0; kk < KP; ++kk)
            ffma2(ca, *reinterpret_cast<const u64*>(c_wc + 2 * kk), h2[e][kk]);
        float cO = hsum2(ca);
        if (valid[e]) {
            if (off_car >= 0) out[off_car + idx[e]] = cO;
            if (off_log >= 0) out[off_log + idx[e] * (TT + 1) + TT] = cO;
        }
    }
}

extern "C" void kernel_launch(void* const* d_in, const int* in_sizes, int n_in,
                              void* d_out, int out_size)
{
    const float* x    = (const float*)d_in[0];
    const float* w_ih = (const float*)d_in[1];
    const float* w_hh = (const float*)d_in[2];
    const float* b_ih = (const float*)d_in[3];
    const float* b_hh = (const float*)d_in[4];
    float* out = (float*)d_out;

    // n-gate rows (32..47) + heads into constant memory (graph-capturable D2D)
    cudaMemcpyToSymbolAsync(c_whhn, (const char*)d_in[2] + 32 * HH * sizeof(float),
                            HH * HH * sizeof(float), 0, cudaMemcpyDeviceToDevice, 0);
    cudaMemcpyToSymbolAsync(c_wihn, (const char*)d_in[1] + 32 * 2 * sizeof(float),
                            HH * 2 * sizeof(float), 0, cudaMemcpyDeviceToDevice, 0);
    cudaMemcpyToSymbolAsync(c_ws, d_in[5], HH * sizeof(float), 0, cudaMemcpyDeviceToDevice, 0);
    cudaMemcpyToSymbolAsync(c_bs, d_in[6], sizeof(float), 0, cudaMemcpyDeviceToDevice, 0);
    cudaMemcpyToSymbolAsync(c_wc, d_in[7], HH * sizeof(float), 0, cudaMemcpyDeviceToDevice, 0);
    cudaMemcpyToSymbolAsync(c_bc, d_in[8], sizeof(float), 0, cudaMemcpyDeviceToDevice, 0);

    const long long HID = 0;
    const long long SUM = (long long)BATCH * TT * HH;          // 67108864
    const long long CAR = SUM + (long long)BATCH * TT;         // 71303168
    const long long LOG = CAR + (long long)BATCH;              // 72351744
    const long long FULL = LOG + (long long)BATCH * (TT + 1);  // 77594624

    long long oh = -1, os = -1, oc = -1, ol = -1;
    long long sz = (long long)out_size;
    if (sz == FULL)                               { oh = HID; os = SUM; oc = CAR; ol = LOG; }
    else if (sz == (long long)BATCH * TT * HH)    { oh = 0; }
    else if (sz == (long long)BATCH * (TT + 1))   { ol = 0; }
    else if (sz == (long long)BATCH * TT)         { os = 0; }
    else if (sz == (long long)BATCH)              { oc = 0; }
    else                                          { oh = HID; os = SUM; oc = CAR; ol = LOG; }

    const int blocks = (BATCH + SPAN - 1) / SPAN;   // 2731
    gru_adder_kernel<<<blocks, THREADS>>>(x, w_ih, w_hh, b_ih, b_hh,
                                          out, oh, os, oc, ol);
}